// round 7
// baseline (speedup 1.0000x reference)
#include <cuda_runtime.h>
#include <cuda_bf16.h>
#include <math.h>
#include <stdint.h>

// Problem constants
#define S_LEN 2048
#define D_DIM 768
#define N_STATE 16
#define N_HEADS 12
#define DH 64
#define WINDOW 128
#define KK 1843            // int((1-0.1)*2048)
#define SPIKE 0.1f
#define FULLM 0xffffffffu

// ---------------------------------------------------------------------------
// Scratch (device globals; no dynamic allocation allowed)
// ---------------------------------------------------------------------------
__device__ float g_gate[S_LEN * D_DIM];
__device__ float g_H[S_LEN * D_DIM];
__device__ float g_Q[S_LEN * D_DIM];
__device__ float g_K[S_LEN * D_DIM];
__device__ float g_V[S_LEN * D_DIM];
__device__ float g_ctx[S_LEN * D_DIM];

// ---------------------------------------------------------------------------
// Split-TF32 helpers (3-MMA emulation of fp32 GEMM on tensor cores)
// ---------------------------------------------------------------------------
__device__ __forceinline__ void split_tf32(float a, uint32_t& hi, uint32_t& lo) {
    asm("cvt.rna.tf32.f32 %0, %1;" : "=r"(hi) : "f"(a));
    float r = a - __uint_as_float(hi);
    asm("cvt.rna.tf32.f32 %0, %1;" : "=r"(lo) : "f"(r));
}

__device__ __forceinline__ void mma8(float c[4], const uint32_t a[4], const uint32_t b[2]) {
    asm("mma.sync.aligned.m16n8k8.row.col.f32.tf32.tf32.f32 "
        "{%0,%1,%2,%3},{%4,%5,%6,%7},{%8,%9},{%0,%1,%2,%3};"
        : "+f"(c[0]), "+f"(c[1]), "+f"(c[2]), "+f"(c[3])
        : "r"(a[0]), "r"(a[1]), "r"(a[2]), "r"(a[3]), "r"(b[0]), "r"(b[1]));
}

#define CPA16(dst, src) asm volatile("cp.async.ca.shared.global [%0], [%1], 16;" :: "r"(dst), "l"(src))
#define CPCOMMIT()      asm volatile("cp.async.commit_group;" ::: "memory")
#define CPWAIT1()       asm volatile("cp.async.wait_group 1;" ::: "memory")
#define CPWAIT0()       asm volatile("cp.async.wait_group 0;" ::: "memory")

// ---------------------------------------------------------------------------
// Tensor-core GEMM (split tf32, 3-MMA), BT=true path only:
//   C[m,n] = alpha * sum_k A[m,k]*B[n,k]  (+bias) (+sigmoid)
// EPI: 0 none, 1 +bias, 2 sigmoid(v+bias)
// Tiles BM=BN=64, BK=32; 256 thr, 8 warps (2m x 4n), warp tile 32x16.
// 2-stage cp.async pipeline. B/bias/C selected by blockIdx.x / nper.
// ---------------------------------------------------------------------------
template<int EPI>
__global__ __launch_bounds__(256)
void gemm_tc(const float* __restrict__ A,
             const float* __restrict__ B0, const float* __restrict__ B1,
             const float* __restrict__ B2,
             const float* __restrict__ bi0, const float* __restrict__ bi1,
             const float* __restrict__ bi2,
             float* __restrict__ C0, float* __restrict__ C1, float* __restrict__ C2,
             int K, int lda, int ldb, int ldc, float alpha, int nper)
{
    int sel  = blockIdx.x / nper;
    int xb   = blockIdx.x % nper;

    const float* B    = (sel == 0) ? B0  : (sel == 1) ? B1  : B2;
    const float* bias = (sel == 0) ? bi0 : (sel == 1) ? bi1 : bi2;
    float*       C    = (sel == 0) ? C0  : (sel == 1) ? C1  : C2;

    const int BK = 32;
    __shared__ float As[2][64 * 36];
    __shared__ float Bs[2][64 * 36];

    int tid  = threadIdx.x;
    int lane = tid & 31;
    int wid  = tid >> 5;
    int wm   = wid >> 2;            // 0..1
    int wn   = wid & 3;             // 0..3
    int g    = lane >> 2;           // 0..7
    int tg   = lane & 3;            // 0..3

    int row0 = blockIdx.y * 64;
    int col0 = xb * 64;

    unsigned asb = (unsigned)__cvta_generic_to_shared(&As[0][0]);
    unsigned bsb = (unsigned)__cvta_generic_to_shared(&Bs[0][0]);

    float c[2][2][4];
#pragma unroll
    for (int mi = 0; mi < 2; mi++)
#pragma unroll
        for (int ni = 0; ni < 2; ni++)
#pragma unroll
            for (int r = 0; r < 4; r++) c[mi][ni][r] = 0.f;

    int T = K / BK;

    auto load_tile = [&](int tk, int st) {
        int k0 = tk * BK;
        unsigned asd = asb + st * (64 * 36 * 4);
        unsigned bsd = bsb + st * (64 * 36 * 4);
#pragma unroll
        for (int i = 0; i < 2; i++) {
            int idx = tid + i * 256;
            int m = idx >> 3, kc = (idx & 7) << 2;
            CPA16(asd + (m * 36 + kc) * 4, &A[(long)(row0 + m) * lda + k0 + kc]);
        }
#pragma unroll
        for (int i = 0; i < 2; i++) {
            int idx = tid + i * 256;
            int n = idx >> 3, kc = (idx & 7) << 2;
            CPA16(bsd + (n * 36 + kc) * 4, &B[(long)(col0 + n) * ldb + k0 + kc]);
        }
        CPCOMMIT();
    };

    load_tile(0, 0);

    for (int t = 0; t < T; t++) {
        if (t + 1 < T) { load_tile(t + 1, (t + 1) & 1); CPWAIT1(); }
        else           { CPWAIT0(); }
        __syncthreads();

        const float* as = As[t & 1];
        const float* bs = Bs[t & 1];
#pragma unroll
        for (int ks = 0; ks < BK; ks += 8) {
            uint32_t ah[2][4], al[2][4];
#pragma unroll
            for (int mi = 0; mi < 2; mi++) {
                int mb = wm * 32 + mi * 16;
                float f0 = as[(mb + g)     * 36 + ks + tg];
                float f1 = as[(mb + g + 8) * 36 + ks + tg];
                float f2 = as[(mb + g)     * 36 + ks + tg + 4];
                float f3 = as[(mb + g + 8) * 36 + ks + tg + 4];
                split_tf32(f0, ah[mi][0], al[mi][0]);
                split_tf32(f1, ah[mi][1], al[mi][1]);
                split_tf32(f2, ah[mi][2], al[mi][2]);
                split_tf32(f3, ah[mi][3], al[mi][3]);
            }
            uint32_t bh[2][2], bl[2][2];
#pragma unroll
            for (int ni = 0; ni < 2; ni++) {
                int nb = wn * 16 + ni * 8 + g;
                float f0 = bs[nb * 36 + ks + tg];
                float f1 = bs[nb * 36 + ks + tg + 4];
                split_tf32(f0, bh[ni][0], bl[ni][0]);
                split_tf32(f1, bh[ni][1], bl[ni][1]);
            }
#pragma unroll
            for (int mi = 0; mi < 2; mi++)
#pragma unroll
                for (int ni = 0; ni < 2; ni++) {
                    mma8(c[mi][ni], ah[mi], bh[ni]);
                    mma8(c[mi][ni], ah[mi], bl[ni]);
                    mma8(c[mi][ni], al[mi], bh[ni]);
                }
        }
        __syncthreads();
    }

    // ---- epilogue ----
#pragma unroll
    for (int mi = 0; mi < 2; mi++) {
#pragma unroll
        for (int ni = 0; ni < 2; ni++) {
            int row = row0 + wm * 32 + mi * 16 + g;
            int col = col0 + wn * 16 + ni * 8 + 2 * tg;
            float v0 = c[mi][ni][0] * alpha;
            float v1 = c[mi][ni][1] * alpha;
            float v2 = c[mi][ni][2] * alpha;
            float v3 = c[mi][ni][3] * alpha;
            if (EPI >= 1) {
                float b0 = bias[col], b1 = bias[col + 1];
                v0 += b0; v1 += b1; v2 += b0; v3 += b1;
            }
            if (EPI == 2) {
                v0 = 1.f / (1.f + expf(-v0));
                v1 = 1.f / (1.f + expf(-v1));
                v2 = 1.f / (1.f + expf(-v2));
                v3 = 1.f / (1.f + expf(-v3));
            }
            *(float2*)&C[(long)row * ldc + col]       = make_float2(v0, v1);
            *(float2*)&C[(long)(row + 8) * ldc + col] = make_float2(v2, v3);
        }
    }
}

// ---------------------------------------------------------------------------
// Fused attention: scores (QK^T/8) -> per-row top-k + local mask + softmax
// -> banded PV, all on a 16-row x 2048-col score stripe held in SMEM.
// Grid: (S_LEN/16, N_HEADS). 256 threads, 8 warps.
// SMEM layout (floats):
//   Ss  [16][2052]     score stripe (padded stride vs bank conflicts)
//   Qs  [16][68]       Q tile; reused as inv16[16] after softmax
//   Kb  [2][4608]      K/V chunk double buffer; reused as hist[16][256]+state
// ---------------------------------------------------------------------------
#define SSTR 2052
#define SM_FLOATS (16*SSTR + 16*68 + 2*4608)

__global__ __launch_bounds__(256)
void attn_fused(const float* __restrict__ Qg, const float* __restrict__ Kg,
                const float* __restrict__ Vg, float* __restrict__ ctx)
{
    extern __shared__ float sm[];
    float*    Ss   = sm;                       // 16*2052
    float*    Qs   = sm + 16 * SSTR;           // 16*68 (later inv16)
    float*    Kb   = Qs + 16 * 68;             // 2*4608
    int*      hist = (int*)Kb;                 // [16][256]
    unsigned* upf  = (unsigned*)Kb + 4096;     // [16]
    int*      ukn  = (int*)Kb + 4112;          // [16]

    int tid = threadIdx.x, lane = tid & 31, wid = tid >> 5;
    int g = lane >> 2, tg = lane & 3;
    int r0 = blockIdx.x * 16;
    int h  = blockIdx.y;
    const float* Qh = Qg + (size_t)r0 * D_DIM + h * DH;
    const float* Kh = Kg + h * DH;
    const float* Vh = Vg + h * DH;

    // ---- load Q tile 16x64 ----
    for (int i = tid; i < 16 * 64; i += 256) {
        int r = i >> 6, c = i & 63;
        Qs[r * 68 + c] = Qh[(size_t)r * D_DIM + c];
    }
    __syncthreads();

    // ---- build Q fragments (8 ksteps, hi/lo) ----
    uint32_t aH[8][4], aL[8][4];
#pragma unroll
    for (int ks = 0; ks < 8; ks++) {
        float f0 = Qs[g * 68 + ks * 8 + tg];
        float f1 = Qs[(g + 8) * 68 + ks * 8 + tg];
        float f2 = Qs[g * 68 + ks * 8 + tg + 4];
        float f3 = Qs[(g + 8) * 68 + ks * 8 + tg + 4];
        split_tf32(f0, aH[ks][0], aL[ks][0]);
        split_tf32(f1, aH[ks][1], aL[ks][1]);
        split_tf32(f2, aH[ks][2], aL[ks][2]);
        split_tf32(f3, aH[ks][3], aL[ks][3]);
    }

    unsigned kbB = (unsigned)__cvta_generic_to_shared(Kb);

    // ---- Phase A: scores = Q K^T / 8 into Ss ----
    auto loadK = [&](int ck, int st) {
        unsigned dst = kbB + st * 4608 * 4;
#pragma unroll
        for (int it = 0; it < 4; it++) {
            int idx = tid + it * 256;
            int row = idx >> 4, c4 = (idx & 15) << 2;
            CPA16(dst + (row * 68 + c4) * 4, &Kh[(size_t)(ck * 64 + row) * D_DIM + c4]);
        }
        CPCOMMIT();
    };

    loadK(0, 0);
    for (int c = 0; c < 32; c++) {
        if (c + 1 < 32) { loadK(c + 1, (c + 1) & 1); CPWAIT1(); }
        else            { CPWAIT0(); }
        __syncthreads();
        const float* kb = Kb + (c & 1) * 4608;
        float accE[4] = {0, 0, 0, 0}, accO[4] = {0, 0, 0, 0};
#pragma unroll
        for (int ks = 0; ks < 8; ks++) {
            float f0 = kb[(wid * 8 + g) * 68 + ks * 8 + tg];
            float f1 = kb[(wid * 8 + g) * 68 + ks * 8 + tg + 4];
            uint32_t bh[2], bl[2];
            split_tf32(f0, bh[0], bl[0]);
            split_tf32(f1, bh[1], bl[1]);
            float* acc = (ks & 1) ? accO : accE;
            mma8(acc, aH[ks], bh);
            mma8(acc, aH[ks], bl);
            mma8(acc, aL[ks], bh);
        }
        int col = c * 64 + wid * 8;
        Ss[g * SSTR + col + 2 * tg]           = (accE[0] + accO[0]) * 0.125f;
        Ss[g * SSTR + col + 2 * tg + 1]       = (accE[1] + accO[1]) * 0.125f;
        Ss[(g + 8) * SSTR + col + 2 * tg]     = (accE[2] + accO[2]) * 0.125f;
        Ss[(g + 8) * SSTR + col + 2 * tg + 1] = (accE[3] + accO[3]) * 0.125f;
        __syncthreads();
    }

    // ---- Phase B: per-row radix top-k (all 16 rows per pass) ----
    int row = tid >> 4, sub = tid & 15;
    if (tid < 16) { upf[tid] = 0; ukn[tid] = KK; }
    __syncthreads();
#pragma unroll
    for (int byte = 3; byte >= 0; --byte) {
        for (int i = tid; i < 4096; i += 256) hist[i] = 0;
        __syncthreads();
        unsigned pm = (byte == 3) ? 0u : (0xFFFFFFFFu << (8 * (byte + 1)));
        unsigned pref = upf[row];
        const float* srow = &Ss[row * SSTR];
#pragma unroll 4
        for (int e = 0; e < 128; e++) {
            int j = sub + 16 * e;
            unsigned bits = __float_as_uint(fabsf(srow[j]));
            if ((bits & pm) == pref)
                atomicAdd(&hist[row * 256 + ((bits >> (8 * byte)) & 255)], 1);
        }
        __syncthreads();
        for (int rr = wid; rr < 16; rr += 8) {
            int kn = ukn[rr];
            int v[8], cum[8], s = 0;
#pragma unroll
            for (int e = 0; e < 8; e++) {
                v[e] = hist[rr * 256 + 255 - (lane * 8 + e)];
                s += v[e]; cum[e] = s;
            }
            int incl = s;
#pragma unroll
            for (int off = 1; off < 32; off <<= 1) {
                int t2 = __shfl_up_sync(FULLM, incl, off);
                if (lane >= off) incl += t2;
            }
            int excl = incl - s;
            bool has = (excl + cum[7]) >= kn && excl < kn;
            unsigned bal = __ballot_sync(FULLM, has);
            int fl = __ffs(bal) - 1;
            if (lane == fl) {
                int e = 0;
                while (excl + cum[e] < kn) e++;
                upf[rr] |= ((unsigned)(255 - (lane * 8 + e))) << (8 * byte);
                ukn[rr] = kn - (excl + cum[e] - v[e]);
            }
        }
        __syncthreads();
    }

    // ---- Phase C: mask + softmax (normalization deferred to PV epilogue) ----
    {
        unsigned T = upf[row];
        int jmaxr = r0 + row + WINDOW;
        float* srow = &Ss[row * SSTR];
        float m = -INFINITY;
#pragma unroll 4
        for (int e = 0; e < 128; e++) {
            int j = sub + 16 * e;
            float s = srow[j];
            bool keep = (j <= jmaxr) && (__float_as_uint(fabsf(s)) >= T);
            float sv = keep ? s : -INFINITY;
            srow[j] = sv;
            m = fmaxf(m, sv);
        }
#pragma unroll
        for (int off = 8; off; off >>= 1)
            m = fmaxf(m, __shfl_xor_sync(FULLM, m, off, 16));
        float z = 0.f;
#pragma unroll 4
        for (int e = 0; e < 128; e++) {
            int j = sub + 16 * e;
            float s = srow[j];
            float ex = (s == -INFINITY) ? 0.f : __expf(s - m);
            srow[j] = ex;
            z += ex;
        }
#pragma unroll
        for (int off = 8; off; off >>= 1)
            z += __shfl_xor_sync(FULLM, z, off, 16);
        if (sub == 0) Qs[row] = (z > 0.f) ? 1.f / z : 0.f;   // inv16
    }
    __syncthreads();

    // ---- Phase D: banded PV -> ctx ----
    int nch = min(32, (r0 + 144 + 63) >> 6);
    auto loadV = [&](int ck, int st) {
        unsigned dst = kbB + st * 4608 * 4;
#pragma unroll
        for (int it = 0; it < 4; it++) {
            int idx = tid + it * 256;
            int rv = idx >> 4, c4 = (idx & 15) << 2;
            CPA16(dst + (rv * 72 + c4) * 4, &Vh[(size_t)(ck * 64 + rv) * D_DIM + c4]);
        }
        CPCOMMIT();
    };

    float accE[4] = {0, 0, 0, 0}, accO[4] = {0, 0, 0, 0};
    int n0 = wid * 8;
    loadV(0, 0);
    for (int c = 0; c < nch; c++) {
        if (c + 1 < nch) { loadV(c + 1, (c + 1) & 1); CPWAIT1(); }
        else             { CPWAIT0(); }
        __syncthreads();
        const float* vb = Kb + (c & 1) * 4608;
#pragma unroll
        for (int ks = 0; ks < 8; ks++) {
            int kk = c * 64 + ks * 8;
            float p0 = Ss[g * SSTR + kk + tg];
            float p1 = Ss[(g + 8) * SSTR + kk + tg];
            float p2 = Ss[g * SSTR + kk + tg + 4];
            float p3 = Ss[(g + 8) * SSTR + kk + tg + 4];
            uint32_t pah[4], pal[4];
            split_tf32(p0, pah[0], pal[0]);
            split_tf32(p1, pah[1], pal[1]);
            split_tf32(p2, pah[2], pal[2]);
            split_tf32(p3, pah[3], pal[3]);
            float v0 = vb[(ks * 8 + tg) * 72 + n0 + g];
            float v1 = vb[(ks * 8 + tg + 4) * 72 + n0 + g];
            uint32_t bh[2], bl[2];
            split_tf32(v0, bh[0], bl[0]);
            split_tf32(v1, bh[1], bl[1]);
            float* acc = (ks & 1) ? accO : accE;
            mma8(acc, pah, bh);
            mma8(acc, pah, bl);
            mma8(acc, pal, bh);
        }
        __syncthreads();
    }
    float i0 = Qs[g], i1 = Qs[g + 8];
    float* o0 = &ctx[(size_t)(r0 + g) * D_DIM + h * DH + n0 + 2 * tg];
    o0[0] = (accE[0] + accO[0]) * i0;
    o0[1] = (accE[1] + accO[1]) * i0;
    float* o1 = &ctx[(size_t)(r0 + g + 8) * D_DIM + h * DH + n0 + 2 * tg];
    o1[0] = (accE[2] + accO[2]) * i1;
    o1[1] = (accE[3] + accO[3]) * i1;
}

// ---------------------------------------------------------------------------
// SSM sequential scan. 16 lanes per channel (lane = state index n).
// ---------------------------------------------------------------------------
__global__ __launch_bounds__(128)
void ssm_kernel(const float* __restrict__ x, const float* __restrict__ gate,
                const float* __restrict__ Amat, const float* __restrict__ Bm,
                const float* __restrict__ Cm, const float* __restrict__ log_dt,
                float* __restrict__ Hout)
{
    int lane = threadIdx.x & 15;
    int d = blockIdx.x * (blockDim.x >> 4) + (threadIdx.x >> 4);
    if (d >= D_DIM) return;

    float Arow[N_STATE];
#pragma unroll
    for (int m = 0; m < N_STATE; m++) Arow[m] = Amat[lane * N_STATE + m];
    float Bn  = Bm[lane * D_DIM + d];
    float Cn  = Cm[d * N_STATE + lane];
    float dtd = fminf(fmaxf(expf(log_dt[d]), 1e-3f), 1e-1f);

    float h  = 0.f;
    float xv = __ldg(&x[d]);
    float gv = __ldg(&gate[d]);

    for (int t = 0; t < S_LEN; t++) {
        float xn = 0.f, gn = 0.f;
        if (t + 1 < S_LEN) {
            xn = __ldg(&x[(t + 1) * D_DIM + d]);
            gn = __ldg(&gate[(t + 1) * D_DIM + d]);
        }
        float p0 = 0.f, p1 = 0.f, p2 = 0.f, p3 = 0.f;
#pragma unroll
        for (int m = 0; m < 4; m++) {
            p0 = fmaf(Arow[m],      __shfl_sync(FULLM, h, m,      16), p0);
            p1 = fmaf(Arow[m + 4],  __shfl_sync(FULLM, h, m + 4,  16), p1);
            p2 = fmaf(Arow[m + 8],  __shfl_sync(FULLM, h, m + 8,  16), p2);
            p3 = fmaf(Arow[m + 12], __shfl_sync(FULLM, h, m + 12, 16), p3);
        }
        float acc = (p0 + p1) + (p2 + p3);
        float sc  = (acc + xv * Bn) * dtd;
        float gm  = (fabsf(sc) > SPIKE) ? gv : 0.f;
        h = fmaf(sc, gm, h);

        float pr = h * Cn;
#pragma unroll
        for (int off = 8; off; off >>= 1)
            pr += __shfl_xor_sync(FULLM, pr, off, 16);
        if (lane == 0) Hout[t * D_DIM + d] = xv + pr;

        xv = xn; gv = gn;
    }
}

// ---------------------------------------------------------------------------
// Launch
// ---------------------------------------------------------------------------
extern "C" void kernel_launch(void* const* d_in, const int* in_sizes, int n_in,
                              void* d_out, int out_size)
{
    const float* x      = (const float*)d_in[0];
    const float* Amat   = (const float*)d_in[1];
    const float* Bm     = (const float*)d_in[2];
    const float* Cm     = (const float*)d_in[3];
    const float* log_dt = (const float*)d_in[4];
    const float* Wg = (const float*)d_in[5];  const float* bg = (const float*)d_in[6];
    const float* Wq = (const float*)d_in[7];  const float* bq = (const float*)d_in[8];
    const float* Wk = (const float*)d_in[9];  const float* bk = (const float*)d_in[10];
    const float* Wv = (const float*)d_in[11]; const float* bv = (const float*)d_in[12];
    const float* Wd = (const float*)d_in[13]; const float* bd = (const float*)d_in[14];
    float* out = (float*)d_out;

    float *gate, *H, *Q, *K, *V, *ctx;
    cudaGetSymbolAddress((void**)&gate, g_gate);
    cudaGetSymbolAddress((void**)&H,    g_H);
    cudaGetSymbolAddress((void**)&Q,    g_Q);
    cudaGetSymbolAddress((void**)&K,    g_K);
    cudaGetSymbolAddress((void**)&V,    g_V);
    cudaGetSymbolAddress((void**)&ctx,  g_ctx);

    const int SMEM_BYTES = SM_FLOATS * 4;   // 172544
    cudaFuncSetAttribute(attn_fused, cudaFuncAttributeMaxDynamicSharedMemorySize, SMEM_BYTES);

    dim3 blk(256);

    // 1) gate = sigmoid(X Wg^T + bg)
    {
        dim3 grid(D_DIM / 64, S_LEN / 64, 1);
        gemm_tc<2><<<grid, blk>>>(x, Wg, Wg, Wg, bg, bg, bg,
            gate, gate, gate, D_DIM, D_DIM, D_DIM, D_DIM, 1.f, D_DIM / 64);
    }
    // 2) SSM scan -> H = x + y
    ssm_kernel<<<D_DIM / 8, 128>>>(x, gate, Amat, Bm, Cm, log_dt, H);

    // 3) Fused Q,K,V projections (B/C selected per x-block)
    {
        dim3 grid(3 * D_DIM / 64, S_LEN / 64, 1);
        gemm_tc<1><<<grid, blk>>>(H, Wq, Wk, Wv, bq, bk, bv,
            Q, K, V, D_DIM, D_DIM, D_DIM, D_DIM, 1.f, D_DIM / 64);
    }
    // 4-6) Fused scores + top-k/mask/softmax + banded PV
    {
        dim3 grid(S_LEN / 16, N_HEADS);
        attn_fused<<<grid, blk, SMEM_BYTES>>>(Q, K, V, ctx);
    }
    // 7) out = ctx Wd^T + bd
    {
        dim3 grid(D_DIM / 64, S_LEN / 64, 1);
        gemm_tc<1><<<grid, blk>>>(ctx, Wd, Wd, Wd, bd, bd, bd,
            out, out, out, D_DIM, D_DIM, D_DIM, D_DIM, 1.f, D_DIM / 64);
    }
}

// round 9
// speedup vs baseline: 1.1174x; 1.1174x over previous
#include <cuda_runtime.h>
#include <cuda_bf16.h>
#include <math.h>
#include <stdint.h>

// Problem constants
#define S_LEN 2048
#define D_DIM 768
#define N_STATE 16
#define N_HEADS 12
#define DH 64
#define WINDOW 128
#define KK 1843            // int((1-0.1)*2048)
#define SPIKE 0.1f
#define FULLM 0xffffffffu

// ---------------------------------------------------------------------------
// Scratch (device globals; no dynamic allocation allowed)
// ---------------------------------------------------------------------------
__device__ float g_gate[S_LEN * D_DIM];
__device__ float g_H[S_LEN * D_DIM];
__device__ float g_Q[S_LEN * D_DIM];
__device__ float g_K[S_LEN * D_DIM];
__device__ float g_V[S_LEN * D_DIM];
__device__ float g_ctx[S_LEN * D_DIM];

// ---------------------------------------------------------------------------
// Split-TF32 helpers (3-MMA emulation of fp32 GEMM on tensor cores)
// ---------------------------------------------------------------------------
__device__ __forceinline__ void split_tf32(float a, uint32_t& hi, uint32_t& lo) {
    asm("cvt.rna.tf32.f32 %0, %1;" : "=r"(hi) : "f"(a));
    float r = a - __uint_as_float(hi);
    asm("cvt.rna.tf32.f32 %0, %1;" : "=r"(lo) : "f"(r));
}

__device__ __forceinline__ void mma8(float c[4], const uint32_t a[4], const uint32_t b[2]) {
    asm("mma.sync.aligned.m16n8k8.row.col.f32.tf32.tf32.f32 "
        "{%0,%1,%2,%3},{%4,%5,%6,%7},{%8,%9},{%0,%1,%2,%3};"
        : "+f"(c[0]), "+f"(c[1]), "+f"(c[2]), "+f"(c[3])
        : "r"(a[0]), "r"(a[1]), "r"(a[2]), "r"(a[3]), "r"(b[0]), "r"(b[1]));
}

#define CPA16(dst, src) asm volatile("cp.async.ca.shared.global [%0], [%1], 16;" :: "r"(dst), "l"(src))
#define CPCOMMIT()      asm volatile("cp.async.commit_group;" ::: "memory")
#define CPWAIT1()       asm volatile("cp.async.wait_group 1;" ::: "memory")
#define CPWAIT0()       asm volatile("cp.async.wait_group 0;" ::: "memory")

// ---------------------------------------------------------------------------
// Tensor-core GEMM (split tf32, 3-MMA), BT path:
//   C[m,n] = alpha * sum_k A[m,k]*B[n,k]  (+bias) (+sigmoid)
// Tiles BM=BN=64, BK=32; 256 thr, 8 warps (2m x 4n), warp tile 32x16.
// 2-stage cp.async pipeline. B/bias/C selected by blockIdx.x / nper.
// ---------------------------------------------------------------------------
template<int EPI>
__global__ __launch_bounds__(256)
void gemm_tc(const float* __restrict__ A,
             const float* __restrict__ B0, const float* __restrict__ B1,
             const float* __restrict__ B2,
             const float* __restrict__ bi0, const float* __restrict__ bi1,
             const float* __restrict__ bi2,
             float* __restrict__ C0, float* __restrict__ C1, float* __restrict__ C2,
             int K, int lda, int ldb, int ldc, float alpha, int nper)
{
    int sel  = blockIdx.x / nper;
    int xb   = blockIdx.x % nper;

    const float* B    = (sel == 0) ? B0  : (sel == 1) ? B1  : B2;
    const float* bias = (sel == 0) ? bi0 : (sel == 1) ? bi1 : bi2;
    float*       C    = (sel == 0) ? C0  : (sel == 1) ? C1  : C2;

    const int BK = 32;
    __shared__ float As[2][64 * 36];
    __shared__ float Bs[2][64 * 36];

    int tid  = threadIdx.x;
    int lane = tid & 31;
    int wid  = tid >> 5;
    int wm   = wid >> 2;
    int wn   = wid & 3;
    int g    = lane >> 2;
    int tg   = lane & 3;

    int row0 = blockIdx.y * 64;
    int col0 = xb * 64;

    unsigned asb = (unsigned)__cvta_generic_to_shared(&As[0][0]);
    unsigned bsb = (unsigned)__cvta_generic_to_shared(&Bs[0][0]);

    float c[2][2][4];
#pragma unroll
    for (int mi = 0; mi < 2; mi++)
#pragma unroll
        for (int ni = 0; ni < 2; ni++)
#pragma unroll
            for (int r = 0; r < 4; r++) c[mi][ni][r] = 0.f;

    int T = K / BK;

    auto load_tile = [&](int tk, int st) {
        int k0 = tk * BK;
        unsigned asd = asb + st * (64 * 36 * 4);
        unsigned bsd = bsb + st * (64 * 36 * 4);
#pragma unroll
        for (int i = 0; i < 2; i++) {
            int idx = tid + i * 256;
            int m = idx >> 3, kc = (idx & 7) << 2;
            CPA16(asd + (m * 36 + kc) * 4, &A[(long)(row0 + m) * lda + k0 + kc]);
        }
#pragma unroll
        for (int i = 0; i < 2; i++) {
            int idx = tid + i * 256;
            int n = idx >> 3, kc = (idx & 7) << 2;
            CPA16(bsd + (n * 36 + kc) * 4, &B[(long)(col0 + n) * ldb + k0 + kc]);
        }
        CPCOMMIT();
    };

    load_tile(0, 0);

    for (int t = 0; t < T; t++) {
        if (t + 1 < T) { load_tile(t + 1, (t + 1) & 1); CPWAIT1(); }
        else           { CPWAIT0(); }
        __syncthreads();

        const float* as = As[t & 1];
        const float* bs = Bs[t & 1];
#pragma unroll
        for (int ks = 0; ks < BK; ks += 8) {
            uint32_t ah[2][4], al[2][4];
#pragma unroll
            for (int mi = 0; mi < 2; mi++) {
                int mb = wm * 32 + mi * 16;
                float f0 = as[(mb + g)     * 36 + ks + tg];
                float f1 = as[(mb + g + 8) * 36 + ks + tg];
                float f2 = as[(mb + g)     * 36 + ks + tg + 4];
                float f3 = as[(mb + g + 8) * 36 + ks + tg + 4];
                split_tf32(f0, ah[mi][0], al[mi][0]);
                split_tf32(f1, ah[mi][1], al[mi][1]);
                split_tf32(f2, ah[mi][2], al[mi][2]);
                split_tf32(f3, ah[mi][3], al[mi][3]);
            }
            uint32_t bh[2][2], bl[2][2];
#pragma unroll
            for (int ni = 0; ni < 2; ni++) {
                int nb = wn * 16 + ni * 8 + g;
                float f0 = bs[nb * 36 + ks + tg];
                float f1 = bs[nb * 36 + ks + tg + 4];
                split_tf32(f0, bh[ni][0], bl[ni][0]);
                split_tf32(f1, bh[ni][1], bl[ni][1]);
            }
#pragma unroll
            for (int mi = 0; mi < 2; mi++)
#pragma unroll
                for (int ni = 0; ni < 2; ni++) {
                    mma8(c[mi][ni], ah[mi], bh[ni]);
                    mma8(c[mi][ni], ah[mi], bl[ni]);
                    mma8(c[mi][ni], al[mi], bh[ni]);
                }
        }
        __syncthreads();
    }

#pragma unroll
    for (int mi = 0; mi < 2; mi++) {
#pragma unroll
        for (int ni = 0; ni < 2; ni++) {
            int row = row0 + wm * 32 + mi * 16 + g;
            int col = col0 + wn * 16 + ni * 8 + 2 * tg;
            float v0 = c[mi][ni][0] * alpha;
            float v1 = c[mi][ni][1] * alpha;
            float v2 = c[mi][ni][2] * alpha;
            float v3 = c[mi][ni][3] * alpha;
            if (EPI >= 1) {
                float b0 = bias[col], b1 = bias[col + 1];
                v0 += b0; v1 += b1; v2 += b0; v3 += b1;
            }
            if (EPI == 2) {
                v0 = 1.f / (1.f + expf(-v0));
                v1 = 1.f / (1.f + expf(-v1));
                v2 = 1.f / (1.f + expf(-v2));
                v3 = 1.f / (1.f + expf(-v3));
            }
            *(float2*)&C[(long)row * ldc + col]       = make_float2(v0, v1);
            *(float2*)&C[(long)(row + 8) * ldc + col] = make_float2(v2, v3);
        }
    }
}

// ---------------------------------------------------------------------------
// Fused attention v2: 512 threads, 16 warps.
// Phase A: scores 16x2048 into SMEM (128-row K chunks, 16 warps parallel)
// Phase B: per-row radix top-k, ONE WARP PER ROW (no block syncs)
// Phase C: mask+softmax, one warp per row (inv kept for epilogue)
// Phase D: banded PV, split-K across two 8-warp groups (named barriers)
// SMEM: Ss[16][2050] | Qs[16*68] | Vb[4][4608] (K uses 2x8704 of Vb;
//       hist[16][256] aliases Vb; group1 partials alias Vb[2])
// ---------------------------------------------------------------------------
#define SSTR 2050
#define SM_FLOATS (16*SSTR + 16*68 + 4*4608)

__global__ __launch_bounds__(512)
void attn_fused(const float* __restrict__ Qg, const float* __restrict__ Kg,
                const float* __restrict__ Vg, float* __restrict__ ctx)
{
    extern __shared__ float sm[];
    float* Ss = sm;                       // 16*2050
    float* Qs = sm + 16 * SSTR;           // 16*68 (later inv16)
    float* Vb = Qs + 16 * 68;             // 4*4608

    int tid = threadIdx.x, lane = tid & 31, wid = tid >> 5;
    int g = lane >> 2, tg = lane & 3;
    int r0 = blockIdx.x * 16;
    int h  = blockIdx.y;
    const float* Qh = Qg + (size_t)r0 * D_DIM + h * DH;
    const float* Kh = Kg + h * DH;
    const float* Vh = Vg + h * DH;

    // ---- load Q tile 16x64 ----
    for (int i = tid; i < 16 * 64; i += 512) {
        int r = i >> 6, c = i & 63;
        Qs[r * 68 + c] = Qh[(size_t)r * D_DIM + c];
    }
    __syncthreads();

    // ---- Q fragments (8 ksteps, hi/lo) ----
    uint32_t aH[8][4], aL[8][4];
#pragma unroll
    for (int ks = 0; ks < 8; ks++) {
        float f0 = Qs[g * 68 + ks * 8 + tg];
        float f1 = Qs[(g + 8) * 68 + ks * 8 + tg];
        float f2 = Qs[g * 68 + ks * 8 + tg + 4];
        float f3 = Qs[(g + 8) * 68 + ks * 8 + tg + 4];
        split_tf32(f0, aH[ks][0], aL[ks][0]);
        split_tf32(f1, aH[ks][1], aL[ks][1]);
        split_tf32(f2, aH[ks][2], aL[ks][2]);
        split_tf32(f3, aH[ks][3], aL[ks][3]);
    }

    unsigned vbB = (unsigned)__cvta_generic_to_shared(Vb);

    // ==== Phase A: scores = Q K^T / 8 (K chunks of 128 rows) ====
    auto loadK = [&](int ck, int st) {
        unsigned dst = vbB + st * 8704 * 4;
#pragma unroll
        for (int it = 0; it < 4; it++) {
            int idx = tid + it * 512;
            int row = idx >> 4, c4 = (idx & 15) << 2;
            CPA16(dst + (row * 68 + c4) * 4, &Kh[(size_t)(ck * 128 + row) * D_DIM + c4]);
        }
        CPCOMMIT();
    };

    loadK(0, 0);
    for (int c = 0; c < 16; c++) {
        if (c + 1 < 16) { loadK(c + 1, (c + 1) & 1); CPWAIT1(); }
        else            { CPWAIT0(); }
        __syncthreads();
        const float* kb = Vb + (c & 1) * 8704;
        float accE[4] = {0, 0, 0, 0}, accO[4] = {0, 0, 0, 0};
#pragma unroll
        for (int ks = 0; ks < 8; ks++) {
            float f0 = kb[(wid * 8 + g) * 68 + ks * 8 + tg];
            float f1 = kb[(wid * 8 + g) * 68 + ks * 8 + tg + 4];
            uint32_t bh[2], bl[2];
            split_tf32(f0, bh[0], bl[0]);
            split_tf32(f1, bh[1], bl[1]);
            float* acc = (ks & 1) ? accO : accE;
            mma8(acc, aH[ks], bh);
            mma8(acc, aH[ks], bl);
            mma8(acc, aL[ks], bh);
        }
        int col = c * 128 + wid * 8;
        Ss[g * SSTR + col + 2 * tg]           = (accE[0] + accO[0]) * 0.125f;
        Ss[g * SSTR + col + 2 * tg + 1]       = (accE[1] + accO[1]) * 0.125f;
        Ss[(g + 8) * SSTR + col + 2 * tg]     = (accE[2] + accO[2]) * 0.125f;
        Ss[(g + 8) * SSTR + col + 2 * tg + 1] = (accE[3] + accO[3]) * 0.125f;
        __syncthreads();
    }

    // ==== Phase B: per-row radix top-k, one warp per row (warp-local) ====
    int* hist = (int*)Vb;                  // K data dead; 16*256 ints
    {
        int rowB = wid;
        const float* srowB = &Ss[rowB * SSTR];
        int* myhist = hist + rowB * 256;
        unsigned prefix = 0;
        int kneed = KK;
#pragma unroll
        for (int byte = 3; byte >= 0; --byte) {
#pragma unroll
            for (int b = lane; b < 256; b += 32) myhist[b] = 0;
            __syncwarp();
            unsigned pm = (byte == 3) ? 0u : (0xFFFFFFFFu << (8 * (byte + 1)));
#pragma unroll 4
            for (int e = 0; e < 64; e++) {
                int j = lane + 32 * e;
                unsigned bits = __float_as_uint(fabsf(srowB[j]));
                if ((bits & pm) == prefix)
                    atomicAdd(&myhist[(bits >> (8 * byte)) & 255], 1);
            }
            __syncwarp();
            int v[8], cum[8], s = 0;
#pragma unroll
            for (int e = 0; e < 8; e++) {
                v[e] = myhist[255 - (lane * 8 + e)];
                s += v[e]; cum[e] = s;
            }
            int incl = s;
#pragma unroll
            for (int off = 1; off < 32; off <<= 1) {
                int t2 = __shfl_up_sync(FULLM, incl, off);
                if (lane >= off) incl += t2;
            }
            int excl = incl - s;
            bool has = (excl + cum[7]) >= kneed && excl < kneed;
            unsigned bal = __ballot_sync(FULLM, has);
            int fl = __ffs(bal) - 1;
            int selB = 0, nk = 0;
            if (lane == fl) {
                int e = 0;
                while (excl + cum[e] < kneed) e++;
                selB = 255 - (lane * 8 + e);
                nk = kneed - (excl + cum[e] - v[e]);
            }
            selB = __shfl_sync(FULLM, selB, fl);
            nk   = __shfl_sync(FULLM, nk, fl);
            prefix |= ((unsigned)selB) << (8 * byte);
            kneed = nk;
        }

        // ==== Phase C: mask + softmax (unnormalized; inv to Qs[row]) ====
        unsigned T = prefix;
        int jmaxr = r0 + rowB + WINDOW;
        float* srow = &Ss[rowB * SSTR];
        float m = -INFINITY;
#pragma unroll 4
        for (int e = 0; e < 64; e++) {
            int j = lane + 32 * e;
            float s = srow[j];
            bool keep = (j <= jmaxr) && (__float_as_uint(fabsf(s)) >= T);
            float sv = keep ? s : -INFINITY;
            srow[j] = sv;
            m = fmaxf(m, sv);
        }
#pragma unroll
        for (int off = 16; off; off >>= 1)
            m = fmaxf(m, __shfl_xor_sync(FULLM, m, off));
        float z = 0.f;
#pragma unroll 4
        for (int e = 0; e < 64; e++) {
            int j = lane + 32 * e;
            float s = srow[j];
            float ex = (s == -INFINITY) ? 0.f : __expf(s - m);
            srow[j] = ex;
            z += ex;
        }
#pragma unroll
        for (int off = 16; off; off >>= 1)
            z += __shfl_xor_sync(FULLM, z, off);
        if (lane == 0) Qs[rowB] = (z > 0.f) ? 1.f / z : 0.f;
    }
    __syncthreads();   // publish exp(Ss) + inv before PV

    // ==== Phase D: banded PV, split-K across 2 groups of 8 warps ====
    int nch = min(32, (r0 + 144 + 63) >> 6);   // 64-row V chunks
    int g2  = wid >> 3;                        // group 0/1
    int lw  = wid & 7;
    int n0  = lw * 8;
    int lt  = tid & 255;
    unsigned myVbB = vbB + g2 * 2 * 4608 * 4;

    auto loadV = [&](int ci, int st) {
        unsigned dst = myVbB + st * 4608 * 4;
#pragma unroll
        for (int it = 0; it < 4; it++) {
            int idx = lt + it * 256;
            int rv = idx >> 4, c4 = (idx & 15) << 2;
            CPA16(dst + (rv * 72 + c4) * 4, &Vh[(size_t)(ci * 64 + rv) * D_DIM + c4]);
        }
        CPCOMMIT();
    };

    float accE[4] = {0, 0, 0, 0}, accO[4] = {0, 0, 0, 0};
    int myCount = (nch - g2 + 1) >> 1;         // chunks g2, g2+2, ...
    const float* myVb = Vb + g2 * 2 * 4608;

    loadV(g2, 0);
    for (int q = 0; q < myCount; q++) {
        int ci = g2 + 2 * q;
        if (q + 1 < myCount) { loadV(ci + 2, (q + 1) & 1); CPWAIT1(); }
        else                 { CPWAIT0(); }
        asm volatile("bar.sync %0, 256;" :: "r"(1 + g2) : "memory");
        const float* vb = myVb + (q & 1) * 4608;
#pragma unroll
        for (int ks = 0; ks < 8; ks++) {
            int kk = ci * 64 + ks * 8;
            float p0 = Ss[g * SSTR + kk + tg];
            float p1 = Ss[(g + 8) * SSTR + kk + tg];
            float p2 = Ss[g * SSTR + kk + tg + 4];
            float p3 = Ss[(g + 8) * SSTR + kk + tg + 4];
            uint32_t pah[4], pal[4];
            split_tf32(p0, pah[0], pal[0]);
            split_tf32(p1, pah[1], pal[1]);
            split_tf32(p2, pah[2], pal[2]);
            split_tf32(p3, pah[3], pal[3]);
            float v0 = vb[(ks * 8 + tg) * 72 + n0 + g];
            float v1 = vb[(ks * 8 + tg + 4) * 72 + n0 + g];
            uint32_t bh[2], bl[2];
            split_tf32(v0, bh[0], bl[0]);
            split_tf32(v1, bh[1], bl[1]);
            float* acc = (ks & 1) ? accO : accE;
            mma8(acc, pah, bh);
            mma8(acc, pah, bl);
            mma8(acc, pal, bh);
        }
        asm volatile("bar.sync %0, 256;" :: "r"(1 + g2) : "memory");
    }

    // group 1 writes partials into its own (dead) buffer region
    float* Ps = Vb + 2 * 4608;                 // 16*64
    if (g2 == 1) {
        Ps[g * 64 + n0 + 2 * tg]           = accE[0] + accO[0];
        Ps[g * 64 + n0 + 2 * tg + 1]       = accE[1] + accO[1];
        Ps[(g + 8) * 64 + n0 + 2 * tg]     = accE[2] + accO[2];
        Ps[(g + 8) * 64 + n0 + 2 * tg + 1] = accE[3] + accO[3];
    }
    __syncthreads();
    if (g2 == 0) {
        float i0 = Qs[g], i1 = Qs[g + 8];
        float r00 = (accE[0] + accO[0] + Ps[g * 64 + n0 + 2 * tg])           * i0;
        float r01 = (accE[1] + accO[1] + Ps[g * 64 + n0 + 2 * tg + 1])       * i0;
        float r10 = (accE[2] + accO[2] + Ps[(g + 8) * 64 + n0 + 2 * tg])     * i1;
        float r11 = (accE[3] + accO[3] + Ps[(g + 8) * 64 + n0 + 2 * tg + 1]) * i1;
        *(float2*)&ctx[(size_t)(r0 + g) * D_DIM + h * DH + n0 + 2 * tg]     = make_float2(r00, r01);
        *(float2*)&ctx[(size_t)(r0 + g + 8) * D_DIM + h * DH + n0 + 2 * tg] = make_float2(r10, r11);
    }
}

// ---------------------------------------------------------------------------
// SSM sequential scan. 16 lanes per channel (lane = state index n).
// ---------------------------------------------------------------------------
__global__ __launch_bounds__(128)
void ssm_kernel(const float* __restrict__ x, const float* __restrict__ gate,
                const float* __restrict__ Amat, const float* __restrict__ Bm,
                const float* __restrict__ Cm, const float* __restrict__ log_dt,
                float* __restrict__ Hout)
{
    int lane = threadIdx.x & 15;
    int d = blockIdx.x * (blockDim.x >> 4) + (threadIdx.x >> 4);
    if (d >= D_DIM) return;

    float Arow[N_STATE];
#pragma unroll
    for (int m = 0; m < N_STATE; m++) Arow[m] = Amat[lane * N_STATE + m];
    float Bn  = Bm[lane * D_DIM + d];
    float Cn  = Cm[d * N_STATE + lane];
    float dtd = fminf(fmaxf(expf(log_dt[d]), 1e-3f), 1e-1f);

    float h  = 0.f;
    float xv = __ldg(&x[d]);
    float gv = __ldg(&gate[d]);

    for (int t = 0; t < S_LEN; t++) {
        float xn = 0.f, gn = 0.f;
        if (t + 1 < S_LEN) {
            xn = __ldg(&x[(t + 1) * D_DIM + d]);
            gn = __ldg(&gate[(t + 1) * D_DIM + d]);
        }
        float p0 = 0.f, p1 = 0.f, p2 = 0.f, p3 = 0.f;
#pragma unroll
        for (int m = 0; m < 4; m++) {
            p0 = fmaf(Arow[m],      __shfl_sync(FULLM, h, m,      16), p0);
            p1 = fmaf(Arow[m + 4],  __shfl_sync(FULLM, h, m + 4,  16), p1);
            p2 = fmaf(Arow[m + 8],  __shfl_sync(FULLM, h, m + 8,  16), p2);
            p3 = fmaf(Arow[m + 12], __shfl_sync(FULLM, h, m + 12, 16), p3);
        }
        float acc = (p0 + p1) + (p2 + p3);
        float sc  = (acc + xv * Bn) * dtd;
        float gm  = (fabsf(sc) > SPIKE) ? gv : 0.f;
        h = fmaf(sc, gm, h);

        float pr = h * Cn;
#pragma unroll
        for (int off = 8; off; off >>= 1)
            pr += __shfl_xor_sync(FULLM, pr, off, 16);
        if (lane == 0) Hout[t * D_DIM + d] = xv + pr;

        xv = xn; gv = gn;
    }
}

// ---------------------------------------------------------------------------
// Launch
// ---------------------------------------------------------------------------
extern "C" void kernel_launch(void* const* d_in, const int* in_sizes, int n_in,
                              void* d_out, int out_size)
{
    const float* x      = (const float*)d_in[0];
    const float* Amat   = (const float*)d_in[1];
    const float* Bm     = (const float*)d_in[2];
    const float* Cm     = (const float*)d_in[3];
    const float* log_dt = (const float*)d_in[4];
    const float* Wg = (const float*)d_in[5];  const float* bg = (const float*)d_in[6];
    const float* Wq = (const float*)d_in[7];  const float* bq = (const float*)d_in[8];
    const float* Wk = (const float*)d_in[9];  const float* bk = (const float*)d_in[10];
    const float* Wv = (const float*)d_in[11]; const float* bv = (const float*)d_in[12];
    const float* Wd = (const float*)d_in[13]; const float* bd = (const float*)d_in[14];
    float* out = (float*)d_out;

    float *gate, *H, *Q, *K, *V, *ctx;
    cudaGetSymbolAddress((void**)&gate, g_gate);
    cudaGetSymbolAddress((void**)&H,    g_H);
    cudaGetSymbolAddress((void**)&Q,    g_Q);
    cudaGetSymbolAddress((void**)&K,    g_K);
    cudaGetSymbolAddress((void**)&V,    g_V);
    cudaGetSymbolAddress((void**)&ctx,  g_ctx);

    const int SMEM_BYTES = SM_FLOATS * 4;   // 209,280
    cudaFuncSetAttribute(attn_fused, cudaFuncAttributeMaxDynamicSharedMemorySize, SMEM_BYTES);

    dim3 blk(256);

    // 1) gate = sigmoid(X Wg^T + bg)
    {
        dim3 grid(D_DIM / 64, S_LEN / 64, 1);
        gemm_tc<2><<<grid, blk>>>(x, Wg, Wg, Wg, bg, bg, bg,
            gate, gate, gate, D_DIM, D_DIM, D_DIM, D_DIM, 1.f, D_DIM / 64);
    }
    // 2) SSM scan -> H = x + y
    ssm_kernel<<<D_DIM / 8, 128>>>(x, gate, Amat, Bm, Cm, log_dt, H);

    // 3) Fused Q,K,V projections
    {
        dim3 grid(3 * D_DIM / 64, S_LEN / 64, 1);
        gemm_tc<1><<<grid, blk>>>(H, Wq, Wk, Wv, bq, bk, bv,
            Q, K, V, D_DIM, D_DIM, D_DIM, D_DIM, 1.f, D_DIM / 64);
    }
    // 4-6) Fused scores + top-k/mask/softmax + banded PV
    {
        dim3 grid(S_LEN / 16, N_HEADS);
        attn_fused<<<grid, 512, SMEM_BYTES>>>(Q, K, V, ctx);
    }
    // 7) out = ctx Wd^T + bd
    {
        dim3 grid(D_DIM / 64, S_LEN / 64, 1);
        gemm_tc<1><<<grid, blk>>>(ctx, Wd, Wd, Wd, bd, bd, bd,
            out, out, out, D_DIM, D_DIM, D_DIM, D_DIM, 1.f, D_DIM / 64);
    }
}